// round 4
// baseline (speedup 1.0000x reference)
#include <cuda_runtime.h>
#include <cstdint>

// ---------------- problem constants ----------------
#define TB      64          // batch
#define NCH     512         // hidden cells
#define INX     48          // lstm x input (C*P*P)
#define TSTEPS  1024        // SY*SX
#define G4      2048        // 4*NCH gate columns
#define K_HH    512
#define K_IH    560         // INX + NCH
#define NSEQ    64          // sequential-worker CTAs (each owns 8 h-cols = 32 gate cols)
#define NPRE    64          // pre-worker CTAs (each owns 32 contiguous gate cols)
#define GRIDSZ  (NSEQ + NPRE)
#define THREADS 128         // 4 warps, each warp owns 16 batch rows
#define RING    64          // Gpre ring slots
#define HSTRIDE ((size_t)TSTEPS * NCH)   // 524288: out batch-row stride
// quad-packed smem strides (words per column), both == 16 (mod 32) -> conflict-free LDS.128
#define SS4     1040        // seq: 64 kt * 16 words used
#define SS4P    1136        // pre: (6 + 64) kt * 16 words used

// ---------------- device scratch (static: allocation-free) ----------------
__device__ float d_X[(size_t)TSTEPS * TB * INX];      // extracted patches  ~12.6 MB
__device__ float d_G[(size_t)RING * TB * G4];         // Gpre ring           32 MB
__device__ int   d_pre_arrive[TSTEPS];
__device__ int   d_seq_arrive;
__device__ volatile int d_seq_done;

// ---------------- helpers ----------------
__device__ __forceinline__ unsigned f2tf(float f) {
    unsigned r;
    asm("cvt.rna.tf32.f32 %0, %1;" : "=r"(r) : "f"(f));
    return r;
}
__device__ __forceinline__ void split_tf(float v, unsigned& hi, unsigned& lo) {
    hi = f2tf(v);
    lo = f2tf(v - __uint_as_float(hi));
}
__device__ __forceinline__ void mma8(float& c0, float& c1, float& c2, float& c3,
                                     unsigned a0, unsigned a1, unsigned a2, unsigned a3,
                                     unsigned b0, unsigned b1) {
    asm volatile(
        "mma.sync.aligned.m16n8k8.row.col.f32.tf32.tf32.f32 "
        "{%0,%1,%2,%3},{%4,%5,%6,%7},{%8,%9},{%0,%1,%2,%3};"
        : "+f"(c0), "+f"(c1), "+f"(c2), "+f"(c3)
        : "r"(a0), "r"(a1), "r"(a2), "r"(a3), "r"(b0), "r"(b1));
}
__device__ __forceinline__ float sigm(float x)  { return 1.0f / (1.0f + __expf(-x)); }
__device__ __forceinline__ float tanh_f(float x){ return 1.0f - 2.0f / (__expf(2.0f * x) + 1.0f); }

// quad position for weight element k' (within a kt-group of 8): {m0_hi,m1_hi,m0_lo,m1_lo}
__device__ __forceinline__ int quad_pos(int kt, int r) {   // r in [0,8)
    return kt * 16 + (r & 3) * 4 + (r >> 2);               // +2 for lo
}

// ---------------- init: reset cross-launch counters (graph-replay safe) ----------------
__global__ void init_k() {
    int i = blockIdx.x * blockDim.x + threadIdx.x;
    if (i < TSTEPS) d_pre_arrive[i] = 0;
    if (i == 0) { d_seq_arrive = 0; d_seq_done = -1; }
}

// ---------------- patch extraction ----------------
__global__ void extract_k(const float* __restrict__ batch) {
    int idx = blockIdx.x * blockDim.x + threadIdx.x;
    const int total = TSTEPS * TB * INX;
    if (idx >= total) return;
    int k = idx % INX;
    int b = (idx / INX) % TB;
    int t = idx / (INX * TB);
    int c = k >> 4, p = (k >> 2) & 3, q = k & 3;
    int i = t >> 5, j = t & 31;
    d_X[idx] = batch[((b * 3 + c) * 128 + (i * 4 + p)) * 128 + (j * 4 + q)];
}

// ---------------- persistent 2D-LSTM kernel ----------------
extern __shared__ unsigned smw[];

__global__ void __launch_bounds__(THREADS, 1)
lstm2d_k(const float* __restrict__ W_ih, const float* __restrict__ W_hh,
         const float* __restrict__ b_ih, const float* __restrict__ b_hh,
         float* __restrict__ out) {
    const int tid  = threadIdx.x;
    const int lane = tid & 31;
    const int w    = tid >> 5;            // warp id: batch rows [w*16, w*16+16)
    const int gid  = lane >> 2;           // mma group id
    const int tig  = lane & 3;            // thread-in-group
    const int bid  = blockIdx.x;
    const int rowb = w * 16;

    if (bid < NSEQ) {
        // ================= SEQUENTIAL WORKER =================
        const int nb = bid * 8;           // owns h-cols [nb, nb+8)

        // W_hh slice -> quad-packed tf32 hi/lo in smem. col_local cl = gg*8 + nn.
        for (int idx = tid; idx < 32 * K_HH; idx += THREADS) {
            int cl = idx / K_HH, k = idx - cl * K_HH;
            int g  = (cl >> 3) * NCH + nb + (cl & 7);
            unsigned hi, lo;
            split_tf(W_hh[(size_t)g * K_HH + k], hi, lo);
            int pos = cl * SS4 + quad_pos(k >> 3, k & 7);
            smw[pos] = hi; smw[pos + 2] = lo;
        }
        __syncthreads();

        float cst[4] = {0.f, 0.f, 0.f, 0.f};
        const int n0 = nb + tig * 2;

        for (int t = 0; t < TSTEPS; t++) {
            if (tid == 0) {
                while (((volatile int*)d_pre_arrive)[t] < NPRE) {}
                while (d_seq_done < t - 1) {}
            }
            __syncthreads();
            __threadfence();

            // init accumulators from Gpre ring slot
            const int slot = t & (RING - 1);
            const float* gp = d_G + (size_t)slot * TB * G4;
            float acc[4][4];
#pragma unroll
            for (int gg = 0; gg < 4; gg++) {
                const float2* p0 = (const float2*)(gp + (size_t)(rowb + gid) * G4 + gg * NCH + n0);
                const float2* p1 = (const float2*)(gp + (size_t)(rowb + gid + 8) * G4 + gg * NCH + n0);
                float2 v0 = __ldcg(p0), v1 = __ldcg(p1);
                acc[gg][0] = v0.x; acc[gg][1] = v0.y;
                acc[gg][2] = v1.x; acc[gg][3] = v1.y;
            }

            if (t > 0) {
                const float* a0p = out + (size_t)(rowb + gid) * HSTRIDE + (size_t)(t - 1) * NCH + tig;
                const float* a1p = a0p + 8 * HSTRIDE;
#pragma unroll 4
                for (int kt = 0; kt < 64; kt++) {
                    const int k0 = kt * 8;
                    unsigned a0h, a0l, a1h, a1l, a2h, a2l, a3h, a3l;
                    split_tf(__ldcg(a0p + k0),     a0h, a0l);
                    split_tf(__ldcg(a1p + k0),     a1h, a1l);
                    split_tf(__ldcg(a0p + k0 + 4), a2h, a2l);
                    split_tf(__ldcg(a1p + k0 + 4), a3h, a3l);
#pragma unroll
                    for (int gg = 0; gg < 4; gg++) {
                        const uint4 q = *(const uint4*)&smw[(gg * 8 + gid) * SS4 + kt * 16 + tig * 4];
                        mma8(acc[gg][0], acc[gg][1], acc[gg][2], acc[gg][3],
                             a0h, a1h, a2h, a3h, q.x, q.y);                 // hi*hi
                        mma8(acc[gg][0], acc[gg][1], acc[gg][2], acc[gg][3],
                             a0h, a1h, a2h, a3h, q.z, q.w);                 // hi*lo
                        mma8(acc[gg][0], acc[gg][1], acc[gg][2], acc[gg][3],
                             a0l, a1l, a2l, a3l, q.x, q.y);                 // lo*hi
                    }
                }
            }

            // activations, c update, h write (gate order: i, f, g, o).
            // out_flat[b][t*NCH + n] = h_t[b][n]  (reference reshape is a flat view)
            {
                const int bb0 = rowb + gid;
#pragma unroll
                for (int half = 0; half < 2; half++) {
                    const int pA = half * 2, pB = half * 2 + 1;
                    float iv0 = acc[0][pA], fv0 = acc[1][pA], gv0 = acc[2][pA], ov0 = acc[3][pA];
                    float iv1 = acc[0][pB], fv1 = acc[1][pB], gv1 = acc[2][pB], ov1 = acc[3][pB];
                    float c0 = sigm(fv0) * cst[pA] + sigm(iv0) * tanh_f(gv0);
                    float c1 = sigm(fv1) * cst[pB] + sigm(iv1) * tanh_f(gv1);
                    cst[pA] = c0; cst[pB] = c1;
                    float2 hh = make_float2(sigm(ov0) * tanh_f(c0), sigm(ov1) * tanh_f(c1));
                    *(float2*)&out[(size_t)(bb0 + half * 8) * HSTRIDE + (size_t)t * NCH + n0] = hh;
                }
            }
            __syncthreads();
            if (tid == 0) {
                __threadfence();
                int old = atomicAdd(&d_seq_arrive, 1);
                if (old == NSEQ * (t + 1) - 1) {
                    __threadfence();
                    d_seq_done = t;                       // release the step
                }
            }
        }
    } else {
        // ================= PRE-WORKER =================
        // Gpre[u] = [x_u, h_{u-32}] @ W_ih^T + (b_ih + b_hh), gate cols [gb, gb+32)
        const int gb = (bid - NSEQ) * 32;

        for (int idx = tid; idx < 32 * K_IH; idx += THREADS) {
            int cl = idx / K_IH, k = idx - cl * K_IH;
            unsigned hi, lo;
            split_tf(W_ih[(size_t)(gb + cl) * K_IH + k], hi, lo);
            int pos;
            if (k < 48) pos = cl * SS4P + quad_pos(k >> 3, k & 7);
            else { int kh = k - 48; pos = cl * SS4P + 96 + quad_pos(kh >> 3, kh & 7); }
            smw[pos] = hi; smw[pos + 2] = lo;
        }
        __syncthreads();

        float bias[4][2];
#pragma unroll
        for (int nt = 0; nt < 4; nt++) {
            int g = gb + nt * 8 + tig * 2;
            bias[nt][0] = b_ih[g] + b_hh[g];
            bias[nt][1] = b_ih[g + 1] + b_hh[g + 1];
        }

        for (int u = 0; u < TSTEPS; u++) {
            float acc[4][4];
#pragma unroll
            for (int nt = 0; nt < 4; nt++) {
                acc[nt][0] = bias[nt][0]; acc[nt][1] = bias[nt][1];
                acc[nt][2] = bias[nt][0]; acc[nt][3] = bias[nt][1];
            }

            // x part (K=48) — independent of recurrence, do before waiting
            {
                const float* xA  = d_X + (size_t)u * TB * INX;
                const float* a0p = xA + (rowb + gid) * INX + tig;
                const float* a1p = a0p + 8 * INX;
#pragma unroll
                for (int kt = 0; kt < 6; kt++) {
                    const int k0 = kt * 8;
                    unsigned a0h, a0l, a1h, a1l, a2h, a2l, a3h, a3l;
                    split_tf(a0p[k0],     a0h, a0l);
                    split_tf(a1p[k0],     a1h, a1l);
                    split_tf(a0p[k0 + 4], a2h, a2l);
                    split_tf(a1p[k0 + 4], a3h, a3l);
#pragma unroll
                    for (int nt = 0; nt < 4; nt++) {
                        const uint4 q = *(const uint4*)&smw[(nt * 8 + gid) * SS4P + kt * 16 + tig * 4];
                        mma8(acc[nt][0], acc[nt][1], acc[nt][2], acc[nt][3],
                             a0h, a1h, a2h, a3h, q.x, q.y);
                        mma8(acc[nt][0], acc[nt][1], acc[nt][2], acc[nt][3],
                             a0h, a1h, a2h, a3h, q.z, q.w);
                        mma8(acc[nt][0], acc[nt][1], acc[nt][2], acc[nt][3],
                             a0l, a1l, a2l, a3l, q.x, q.y);
                    }
                }
            }

            if (u >= 32) {
                if (tid == 0) { while (d_seq_done < u - 32) {} }
                __syncthreads();
                __threadfence();

                const float* a0p = out + (size_t)(rowb + gid) * HSTRIDE + (size_t)(u - 32) * NCH + tig;
                const float* a1p = a0p + 8 * HSTRIDE;
#pragma unroll 4
                for (int kt = 0; kt < 64; kt++) {
                    const int k0 = kt * 8;
                    unsigned a0h, a0l, a1h, a1l, a2h, a2l, a3h, a3l;
                    split_tf(__ldcg(a0p + k0),     a0h, a0l);
                    split_tf(__ldcg(a1p + k0),     a1h, a1l);
                    split_tf(__ldcg(a0p + k0 + 4), a2h, a2l);
                    split_tf(__ldcg(a1p + k0 + 4), a3h, a3l);
#pragma unroll
                    for (int nt = 0; nt < 4; nt++) {
                        const uint4 q = *(const uint4*)&smw[(nt * 8 + gid) * SS4P + 96 + kt * 16 + tig * 4];
                        mma8(acc[nt][0], acc[nt][1], acc[nt][2], acc[nt][3],
                             a0h, a1h, a2h, a3h, q.x, q.y);
                        mma8(acc[nt][0], acc[nt][1], acc[nt][2], acc[nt][3],
                             a0h, a1h, a2h, a3h, q.z, q.w);
                        mma8(acc[nt][0], acc[nt][1], acc[nt][2], acc[nt][3],
                             a0l, a1l, a2l, a3l, q.x, q.y);
                    }
                }
            }

            // store Gpre slice (slot u%64 free: consumer step u-64 finished since d_seq_done >= u-32)
            const int slot = u & (RING - 1);
            float* gp = d_G + (size_t)slot * TB * G4;
#pragma unroll
            for (int nt = 0; nt < 4; nt++) {
                float* p0 = gp + (size_t)(rowb + gid) * G4 + gb + nt * 8 + tig * 2;
                *(float2*)p0              = make_float2(acc[nt][0], acc[nt][1]);
                *(float2*)(p0 + 8 * G4)   = make_float2(acc[nt][2], acc[nt][3]);
            }
            __syncthreads();
            if (tid == 0) {
                __threadfence();
                atomicAdd(&d_pre_arrive[u], 1);
            }
        }
    }
}

// ---------------- launch ----------------
extern "C" void kernel_launch(void* const* d_in, const int* in_sizes, int n_in,
                              void* d_out, int out_size) {
    const float* batch = (const float*)d_in[0];
    const float* W_ih  = (const float*)d_in[1];
    const float* W_hh  = (const float*)d_in[2];
    const float* b_ih  = (const float*)d_in[3];
    const float* b_hh  = (const float*)d_in[4];
    float* out = (float*)d_out;

    const int smem = 32 * SS4P * 4;   // 145408 B (covers both roles)
    cudaFuncSetAttribute(lstm2d_k, cudaFuncAttributeMaxDynamicSharedMemorySize, smem);

    init_k<<<4, 256>>>();
    const int tot = TSTEPS * TB * INX;
    extract_k<<<(tot + 255) / 256, 256>>>(batch);
    lstm2d_k<<<GRIDSZ, THREADS, smem>>>(W_ih, W_hh, b_ih, b_hh, out);
}

// round 5
// speedup vs baseline: 1.5307x; 1.5307x over previous
#include <cuda_runtime.h>
#include <cuda_bf16.h>
#include <cstdint>

// ---------------- problem constants ----------------
#define TB      64          // batch
#define NCH     512         // hidden cells
#define INX     48          // lstm x input (C*P*P)
#define TSTEPS  1024        // SY*SX
#define G4      2048        // 4*NCH gate columns
#define K_IH    560         // INX + NCH
#define NSEQ    64          // sequential-worker CTAs (each owns 8 h-cols = 32 gate cols)
#define NPRE    64          // pre-worker CTAs (each owns 32 contiguous gate cols)
#define GRIDSZ  (NSEQ + NPRE)
#define THREADS 128         // 4 warps, each warp owns 16 batch rows
#define RING    64          // Gpre ring slots
#define HSTRIDE ((size_t)TSTEPS * NCH)   // out batch-row stride (flat [t][n] view)
// smem words per weight column; S/4 == 4 (mod 32) -> conflict-free LDS.128
#define S_SEQ   528         // seq: 32 kt16 * 16 words used
#define S_PRE   656         // pre: 35 kt16 * 16 words used

// ---------------- device scratch (static: allocation-free) ----------------
__device__ float d_X[(size_t)TSTEPS * TB * INX];           // patches ~12.6 MB
__device__ float d_G[(size_t)RING * TB * G4];              // Gpre ring 32 MB
__device__ __nv_bfloat16 d_Hhi[(size_t)TSTEPS * TB * NCH]; // h hi parts 64 MB
__device__ __nv_bfloat16 d_Hlo[(size_t)TSTEPS * TB * NCH]; // h lo parts 64 MB
__device__ volatile int d_h_done[NSEQ];  // last step whose h slice CTA i published
__device__ volatile int d_g_done[NPRE];  // last step whose Gpre slice CTA j published

// ---------------- helpers ----------------
__device__ __forceinline__ uint32_t pack2(float e0, float e1) {   // e0 -> low half
    uint32_t d;
    asm("cvt.rn.bf16x2.f32 %0, %1, %2;" : "=r"(d) : "f"(e1), "f"(e0));
    return d;
}
__device__ __forceinline__ uint32_t lo_res(uint32_t hp, float e0, float e1) {
    float h0 = __uint_as_float(hp << 16);
    float h1 = __uint_as_float(hp & 0xFFFF0000u);
    return pack2(e0 - h0, e1 - h1);
}
__device__ __forceinline__ void mma16(float* c,
                                      uint32_t a0, uint32_t a1, uint32_t a2, uint32_t a3,
                                      uint32_t b0, uint32_t b1) {
    asm volatile(
        "mma.sync.aligned.m16n8k16.row.col.f32.bf16.bf16.f32 "
        "{%0,%1,%2,%3},{%4,%5,%6,%7},{%8,%9},{%0,%1,%2,%3};"
        : "+f"(c[0]), "+f"(c[1]), "+f"(c[2]), "+f"(c[3])
        : "r"(a0), "r"(a1), "r"(a2), "r"(a3), "r"(b0), "r"(b1));
}
__device__ __forceinline__ float sigm(float x)  { return 1.0f / (1.0f + __expf(-x)); }
__device__ __forceinline__ float tanh_f(float x){ return 1.0f - 2.0f / (__expf(2.0f * x) + 1.0f); }

// smem packing position for an even k0 (pair k0,k0+1):
//   kt = k0>>4, r = k0&15, s = r>>2, wsel = (r>>1)&1
//   hi word at cl*S + kt*16 + s*4 + wsel, lo word at +2
// fragment read: uint4 at cl*S + kt*16 + s*4 -> {whi_b0, whi_b1, wlo_b0, wlo_b1}
// (k permutation: b0 covers true k {4s,4s+1}, b1 covers {4s+2,4s+3})

// ---------------- init (graph-replay safe) ----------------
__global__ void init_k() {
    int i = threadIdx.x;
    if (i < NSEQ) d_h_done[i] = -1;
    if (i < NPRE) d_g_done[i] = -1;
}

// ---------------- patch extraction ----------------
__global__ void extract_k(const float* __restrict__ batch) {
    int idx = blockIdx.x * blockDim.x + threadIdx.x;
    const int total = TSTEPS * TB * INX;
    if (idx >= total) return;
    int k = idx % INX;
    int b = (idx / INX) % TB;
    int t = idx / (INX * TB);
    int c = k >> 4, p = (k >> 2) & 3, q = k & 3;
    int i = t >> 5, j = t & 31;
    d_X[idx] = batch[((b * 3 + c) * 128 + (i * 4 + p)) * 128 + (j * 4 + q)];
}

// ---------------- persistent 2D-LSTM kernel ----------------
extern __shared__ uint32_t smw[];

__global__ void __launch_bounds__(THREADS, 1)
lstm2d_k(const float* __restrict__ W_ih, const float* __restrict__ W_hh,
         const float* __restrict__ b_ih, const float* __restrict__ b_hh,
         float* __restrict__ out) {
    const int tid  = threadIdx.x;
    const int lane = tid & 31;
    const int w    = tid >> 5;            // warp id: batch rows [w*16, w*16+16)
    const int gid  = lane >> 2;           // mma group id (g)
    const int tig  = lane & 3;            // thread-in-group (s)
    const int bid  = blockIdx.x;
    const int rowb = w * 16;
    const int row0 = rowb + gid;
    const int row1 = row0 + 8;

    if (bid < NSEQ) {
        // ================= SEQUENTIAL WORKER =================
        const int nb = bid * 8;           // owns h-cols [nb, nb+8)

        // W_hh slice -> smem bf16 hi/lo quads. col cl = gate*8 + c.
        for (int idx = tid; idx < 32 * 256; idx += THREADS) {
            int cl = idx >> 8, p = idx & 255, k0 = p * 2;
            int grow = (cl >> 3) * NCH + nb + (cl & 7);
            float w0 = W_hh[(size_t)grow * NCH + k0];
            float w1 = W_hh[(size_t)grow * NCH + k0 + 1];
            uint32_t hi = pack2(w0, w1);
            uint32_t lo = lo_res(hi, w0, w1);
            int kt = k0 >> 4, r = k0 & 15;
            int pos = cl * S_SEQ + kt * 16 + (r >> 2) * 4 + ((r >> 1) & 1);
            smw[pos] = hi; smw[pos + 2] = lo;
        }
        __syncthreads();

        float cst[4] = {0.f, 0.f, 0.f, 0.f};
        const int n0 = nb + tig * 2;
        const int gdep = (tid < 4) ? (tid * 16 + (bid >> 2)) : 0;

        for (int t = 0; t < TSTEPS; t++) {
            // wait for this step's Gpre slice (4 producer CTAs)
            if (tid < 4) { while (d_g_done[gdep] < t) {} }
            __threadfence();
            __syncthreads();

            // init accumulators from Gpre ring slot (issue loads, overlap with h wait)
            const int slot = t & (RING - 1);
            const float* gp = d_G + (size_t)slot * TB * G4;
            float acc[4][4];
#pragma unroll
            for (int gg = 0; gg < 4; gg++) {
                float2 v0 = __ldcg((const float2*)(gp + (size_t)row0 * G4 + gg * NCH + n0));
                float2 v1 = __ldcg((const float2*)(gp + (size_t)row1 * G4 + gg * NCH + n0));
                acc[gg][0] = v0.x; acc[gg][1] = v0.y;
                acc[gg][2] = v1.x; acc[gg][3] = v1.y;
            }

            if (t > 0) {
                // wait for full h_{t-1} (64 producer CTAs, one flag per thread)
                if (tid < NSEQ) { while (d_h_done[tid] < t - 1) {} }
                __threadfence();
                __syncthreads();

                const size_t hb = (size_t)(t - 1) * TB * NCH;
                const uint2* phi0 = (const uint2*)(d_Hhi + hb + (size_t)row0 * NCH + 4 * tig);
                const uint2* phi1 = (const uint2*)(d_Hhi + hb + (size_t)row1 * NCH + 4 * tig);
                const uint2* plo0 = (const uint2*)(d_Hlo + hb + (size_t)row0 * NCH + 4 * tig);
                const uint2* plo1 = (const uint2*)(d_Hlo + hb + (size_t)row1 * NCH + 4 * tig);
#pragma unroll 4
                for (int kt = 0; kt < 32; kt++) {
                    uint2 ah0 = phi0[kt * 4];
                    uint2 ah1 = phi1[kt * 4];
                    uint2 al0 = plo0[kt * 4];
                    uint2 al1 = plo1[kt * 4];
#pragma unroll
                    for (int gg = 0; gg < 4; gg++) {
                        const uint4 q = *(const uint4*)&smw[(gg * 8 + gid) * S_SEQ + kt * 16 + tig * 4];
                        mma16(acc[gg], ah0.x, ah1.x, ah0.y, ah1.y, q.x, q.y);   // hi*Whi
                        mma16(acc[gg], ah0.x, ah1.x, ah0.y, ah1.y, q.z, q.w);   // hi*Wlo
                        mma16(acc[gg], al0.x, al1.x, al0.y, al1.y, q.x, q.y);   // lo*Whi
                    }
                }
            }

            // activations + h publish (gate order i,f,g,o); out[b][t*512+n] flat
#pragma unroll
            for (int half = 0; half < 2; half++) {
                const int pA = half * 2, pB = half * 2 + 1;
                const int bb = row0 + half * 8;
                float iv0 = acc[0][pA], fv0 = acc[1][pA], gv0 = acc[2][pA], ov0 = acc[3][pA];
                float iv1 = acc[0][pB], fv1 = acc[1][pB], gv1 = acc[2][pB], ov1 = acc[3][pB];
                float c0 = sigm(fv0) * cst[pA] + sigm(iv0) * tanh_f(gv0);
                float c1 = sigm(fv1) * cst[pB] + sigm(iv1) * tanh_f(gv1);
                cst[pA] = c0; cst[pB] = c1;
                float h0 = sigm(ov0) * tanh_f(c0);
                float h1 = sigm(ov1) * tanh_f(c1);
                *(float2*)&out[(size_t)bb * HSTRIDE + (size_t)t * NCH + n0] = make_float2(h0, h1);
                uint32_t hp = pack2(h0, h1);
                uint32_t lp = lo_res(hp, h0, h1);
                size_t hidx = ((size_t)t * TB + bb) * NCH + n0;
                *(uint32_t*)(d_Hhi + hidx) = hp;
                *(uint32_t*)(d_Hlo + hidx) = lp;
            }
            __threadfence();
            __syncthreads();
            if (tid == 0) d_h_done[bid] = t;       // release h_t slice
        }
    } else {
        // ================= PRE-WORKER =================
        // Gpre[u] = [x_u, h_{u-32}] @ W_ih^T + (b_ih+b_hh), gate cols [gb, gb+32)
        const int pid = bid - NSEQ;
        const int gb  = pid * 32;

        for (int idx = tid; idx < 32 * 280; idx += THREADS) {
            int cl = idx / 280, p = idx - cl * 280, k0 = p * 2;
            float w0 = W_ih[(size_t)(gb + cl) * K_IH + k0];
            float w1 = W_ih[(size_t)(gb + cl) * K_IH + k0 + 1];
            uint32_t hi = pack2(w0, w1);
            uint32_t lo = lo_res(hi, w0, w1);
            int kt = k0 >> 4, r = k0 & 15;
            int pos = cl * S_PRE + kt * 16 + (r >> 2) * 4 + ((r >> 1) & 1);
            smw[pos] = hi; smw[pos + 2] = lo;
        }
        __syncthreads();

        float bias[4][2];
#pragma unroll
        for (int nt = 0; nt < 4; nt++) {
            int g = gb + nt * 8 + tig * 2;
            bias[nt][0] = b_ih[g] + b_hh[g];
            bias[nt][1] = b_ih[g + 1] + b_hh[g + 1];
        }

        for (int u = 0; u < TSTEPS; u++) {
            float acc[4][4];
#pragma unroll
            for (int nt = 0; nt < 4; nt++) {
                acc[nt][0] = bias[nt][0]; acc[nt][1] = bias[nt][1];
                acc[nt][2] = bias[nt][0]; acc[nt][3] = bias[nt][1];
            }

            // x part (K=48, kt 0..2) — independent of recurrence, runs before waiting
            {
                const float4* xp0 = (const float4*)(d_X + (size_t)u * TB * INX + row0 * INX + 4 * tig);
                const float4* xp1 = (const float4*)(d_X + (size_t)u * TB * INX + row1 * INX + 4 * tig);
#pragma unroll
                for (int kt = 0; kt < 3; kt++) {
                    float4 f0 = xp0[kt * 4];
                    float4 f1 = xp1[kt * 4];
                    uint32_t ah0 = pack2(f0.x, f0.y), ah2 = pack2(f0.z, f0.w);
                    uint32_t ah1 = pack2(f1.x, f1.y), ah3 = pack2(f1.z, f1.w);
                    uint32_t al0 = lo_res(ah0, f0.x, f0.y), al2 = lo_res(ah2, f0.z, f0.w);
                    uint32_t al1 = lo_res(ah1, f1.x, f1.y), al3 = lo_res(ah3, f1.z, f1.w);
#pragma unroll
                    for (int nt = 0; nt < 4; nt++) {
                        const uint4 q = *(const uint4*)&smw[(nt * 8 + gid) * S_PRE + kt * 16 + tig * 4];
                        mma16(acc[nt], ah0, ah1, ah2, ah3, q.x, q.y);
                        mma16(acc[nt], ah0, ah1, ah2, ah3, q.z, q.w);
                        mma16(acc[nt], al0, al1, al2, al3, q.x, q.y);
                    }
                }
            }

            if (u >= 32) {
                if (tid < NSEQ) { while (d_h_done[tid] < u - 32) {} }
                __threadfence();
                __syncthreads();

                const size_t hb = (size_t)(u - 32) * TB * NCH;
                const uint2* phi0 = (const uint2*)(d_Hhi + hb + (size_t)row0 * NCH + 4 * tig);
                const uint2* phi1 = (const uint2*)(d_Hhi + hb + (size_t)row1 * NCH + 4 * tig);
                const uint2* plo0 = (const uint2*)(d_Hlo + hb + (size_t)row0 * NCH + 4 * tig);
                const uint2* plo1 = (const uint2*)(d_Hlo + hb + (size_t)row1 * NCH + 4 * tig);
#pragma unroll 4
                for (int kt = 0; kt < 32; kt++) {
                    uint2 ah0 = phi0[kt * 4];
                    uint2 ah1 = phi1[kt * 4];
                    uint2 al0 = plo0[kt * 4];
                    uint2 al1 = plo1[kt * 4];
#pragma unroll
                    for (int nt = 0; nt < 4; nt++) {
                        const uint4 q = *(const uint4*)&smw[(nt * 8 + gid) * S_PRE + (kt + 3) * 16 + tig * 4];
                        mma16(acc[nt], ah0.x, ah1.x, ah0.y, ah1.y, q.x, q.y);
                        mma16(acc[nt], ah0.x, ah1.x, ah0.y, ah1.y, q.z, q.w);
                        mma16(acc[nt], al0.x, al1.x, al0.y, al1.y, q.x, q.y);
                    }
                }
            }

            // store Gpre slice (slot u%64 is free: all consumers are past step u-64)
            const int slot = u & (RING - 1);
            float* gp = d_G + (size_t)slot * TB * G4;
#pragma unroll
            for (int nt = 0; nt < 4; nt++) {
                float* p0 = gp + (size_t)row0 * G4 + gb + nt * 8 + tig * 2;
                float* p1 = gp + (size_t)row1 * G4 + gb + nt * 8 + tig * 2;
                *(float2*)p0 = make_float2(acc[nt][0], acc[nt][1]);
                *(float2*)p1 = make_float2(acc[nt][2], acc[nt][3]);
            }
            __threadfence();
            __syncthreads();
            if (tid == 0) d_g_done[pid] = u;       // release Gpre[u] slice
        }
    }
}

// ---------------- launch ----------------
extern "C" void kernel_launch(void* const* d_in, const int* in_sizes, int n_in,
                              void* d_out, int out_size) {
    const float* batch = (const float*)d_in[0];
    const float* W_ih  = (const float*)d_in[1];
    const float* W_hh  = (const float*)d_in[2];
    const float* b_ih  = (const float*)d_in[3];
    const float* b_hh  = (const float*)d_in[4];
    float* out = (float*)d_out;

    const int smem = 32 * S_PRE * 4;   // 83968 B (covers both roles)
    cudaFuncSetAttribute(lstm2d_k, cudaFuncAttributeMaxDynamicSharedMemorySize, smem);

    init_k<<<1, 64>>>();
    const int tot = TSTEPS * TB * INX;
    extract_k<<<(tot + 255) / 256, 256>>>(batch);
    lstm2d_k<<<GRIDSZ, THREADS, smem>>>(W_ih, W_hh, b_ih, b_hh, out);
}

// round 6
// speedup vs baseline: 1.8007x; 1.1764x over previous
#include <cuda_runtime.h>
#include <cuda_bf16.h>
#include <cstdint>

// ---------------- problem constants ----------------
#define TB      64          // batch
#define NCH     512         // hidden cells
#define TSTEPS  1024        // SY*SX
#define G4      2048        // 4*NCH gate columns
#define K_IH    560         // 48 + NCH
#define NSEQ    64          // sequential-worker CTAs (8 h-cols = 32 gate cols each)
#define NPRE    64          // pre-worker CTAs (32 contiguous gate cols each)
#define GRIDSZ  (NSEQ + NPRE)
#define THREADS 128         // 4 warps; warp w owns batch rows [16w,16w+16)
#define HSTRIDE ((size_t)TSTEPS * NCH)  // out batch-row stride (flat [t][n] view)
#define S_SEQ   528         // smem words/col for K=512 (33*16, ==16 mod 32 -> conflict-free LDS.128)
#define S_X     48          // smem words/col for K=48 (==16 mod 32)

// ---------------- device scratch (static: allocation-free) ----------------
__device__ float d_G[(size_t)TSTEPS * TB * G4];        // gate pre-activations, 512 MB
__device__ uint4 d_Hq[(size_t)TSTEPS * TB * 128];      // h: {hi2,hi2,lo2,lo2} per 4 cells, 128 MB
__device__ int   d_h_done[NSEQ];
__device__ int   d_g_done[NPRE];

// ---------------- helpers ----------------
__device__ __forceinline__ uint32_t pack2(float e0, float e1) {   // e0 -> low half
    uint32_t d;
    asm("cvt.rn.bf16x2.f32 %0, %1, %2;" : "=r"(d) : "f"(e1), "f"(e0));
    return d;
}
__device__ __forceinline__ uint32_t lo_res(uint32_t hp, float e0, float e1) {
    float h0 = __uint_as_float(hp << 16);
    float h1 = __uint_as_float(hp & 0xFFFF0000u);
    return pack2(e0 - h0, e1 - h1);
}
__device__ __forceinline__ void mma16(float* c,
                                      uint32_t a0, uint32_t a1, uint32_t a2, uint32_t a3,
                                      uint32_t b0, uint32_t b1) {
    asm volatile(
        "mma.sync.aligned.m16n8k16.row.col.f32.bf16.bf16.f32 "
        "{%0,%1,%2,%3},{%4,%5,%6,%7},{%8,%9},{%0,%1,%2,%3};"
        : "+f"(c[0]), "+f"(c[1]), "+f"(c[2]), "+f"(c[3])
        : "r"(a0), "r"(a1), "r"(a2), "r"(a3), "r"(b0), "r"(b1));
}
__device__ __forceinline__ int ld_acq(const int* p) {
    int v;
    asm volatile("ld.acquire.gpu.global.b32 %0, [%1];" : "=r"(v) : "l"(p) : "memory");
    return v;
}
__device__ __forceinline__ void st_rel(int* p, int v) {
    asm volatile("st.release.gpu.global.b32 [%0], %1;" :: "l"(p), "r"(v) : "memory");
}
__device__ __forceinline__ float sigm(float x)  { return 1.0f / (1.0f + __expf(-x)); }
__device__ __forceinline__ float tanh_f(float x){ return 1.0f - 2.0f / (__expf(2.0f * x) + 1.0f); }

// weight pair (k0,k0+1), k0 even -> smem position (k-permuted to match A fragments):
//   kt=k0>>4, r=k0&15: pos = cl*S + kt*16 + (r>>2)*4 + ((r>>1)&1); lo at +2
__device__ __forceinline__ int wpos(int cl, int S, int k0) {
    int kt = k0 >> 4, r = k0 & 15;
    return cl * S + kt * 16 + (r >> 2) * 4 + ((r >> 1) & 1);
}

// ---------------- init (graph-replay safe) ----------------
__global__ void init_k() {
    int i = threadIdx.x;
    if (i < NSEQ) d_h_done[i] = -1;
    if (i < NPRE) d_g_done[i] = 31;   // G[0..31] have no h part: ready after xc_k
}

// ---------------- Xc precompute: G[t] = bias + x_t @ W_ih[:, :48]^T ----------------
__global__ void __launch_bounds__(THREADS)
xc_k(const float* __restrict__ batch, const float* __restrict__ W_ih,
     const float* __restrict__ b_ih, const float* __restrict__ b_hh) {
    __shared__ uint32_t sw[32 * S_X];
    const int tid = threadIdx.x;
    const int lane = tid & 31, w = tid >> 5;
    const int gid = lane >> 2, tig = lane & 3;
    const int row0 = w * 16 + gid, row1 = row0 + 8;
    const int gb = blockIdx.x * 32;

    for (int idx = tid; idx < 32 * 24; idx += THREADS) {
        int cl = idx / 24, k0 = (idx - cl * 24) * 2;
        float w0 = W_ih[(size_t)(gb + cl) * K_IH + k0];
        float w1 = W_ih[(size_t)(gb + cl) * K_IH + k0 + 1];
        uint32_t hi = pack2(w0, w1);
        int pos = wpos(cl, S_X, k0);
        sw[pos] = hi; sw[pos + 2] = lo_res(hi, w0, w1);
    }
    __syncthreads();

    float bias[4][2];
#pragma unroll
    for (int nt = 0; nt < 4; nt++) {
        int g = gb + nt * 8 + tig * 2;
        bias[nt][0] = b_ih[g] + b_hh[g];
        bias[nt][1] = b_ih[g + 1] + b_hh[g + 1];
    }

    for (int us = 0; us < 64; us++) {
        const int u = blockIdx.y * 64 + us;
        const int i = u >> 5, j = u & 31;
        float acc[4][4];
#pragma unroll
        for (int nt = 0; nt < 4; nt++) {
            acc[nt][0] = bias[nt][0]; acc[nt][1] = bias[nt][1];
            acc[nt][2] = bias[nt][0]; acc[nt][3] = bias[nt][1];
        }
#pragma unroll
        for (int kt = 0; kt < 3; kt++) {       // c = kt, p = tig, q = 0..3
            float4 f0 = *(const float4*)&batch[(((size_t)row0 * 3 + kt) * 128 + i * 4 + tig) * 128 + j * 4];
            float4 f1 = *(const float4*)&batch[(((size_t)row1 * 3 + kt) * 128 + i * 4 + tig) * 128 + j * 4];
            uint32_t ah0 = pack2(f0.x, f0.y), ah2 = pack2(f0.z, f0.w);
            uint32_t ah1 = pack2(f1.x, f1.y), ah3 = pack2(f1.z, f1.w);
            uint32_t al0 = lo_res(ah0, f0.x, f0.y), al2 = lo_res(ah2, f0.z, f0.w);
            uint32_t al1 = lo_res(ah1, f1.x, f1.y), al3 = lo_res(ah3, f1.z, f1.w);
#pragma unroll
            for (int nt = 0; nt < 4; nt++) {
                const uint4 q = *(const uint4*)&sw[(nt * 8 + gid) * S_X + kt * 16 + tig * 4];
                mma16(acc[nt], ah0, ah1, ah2, ah3, q.x, q.y);
                mma16(acc[nt], ah0, ah1, ah2, ah3, q.z, q.w);
                mma16(acc[nt], al0, al1, al2, al3, q.x, q.y);
            }
        }
        float* gp = d_G + (size_t)u * TB * G4;
#pragma unroll
        for (int nt = 0; nt < 4; nt++) {
            float* p0 = gp + (size_t)row0 * G4 + gb + nt * 8 + tig * 2;
            float* p1 = gp + (size_t)row1 * G4 + gb + nt * 8 + tig * 2;
            *(float2*)p0 = make_float2(acc[nt][0], acc[nt][1]);
            *(float2*)p1 = make_float2(acc[nt][2], acc[nt][3]);
        }
    }
}

// ---------------- persistent 2D-LSTM kernel ----------------
extern __shared__ uint32_t smw[];

__global__ void __launch_bounds__(THREADS, 1)
lstm2d_k(const float* __restrict__ W_ih, const float* __restrict__ W_hh,
         float* __restrict__ out) {
    const int tid  = threadIdx.x;
    const int lane = tid & 31;
    const int w    = tid >> 5;
    const int gid  = lane >> 2;
    const int tig  = lane & 3;
    const int bid  = blockIdx.x;
    const int row0 = w * 16 + gid;
    const int row1 = row0 + 8;
    const bool seq = (bid < NSEQ);

    // ---- weights (K=512) -> smem bf16 hi/lo quads. seq: W_hh; pre: W_ih[:,48:560] ----
    {
        const int nb32 = seq ? bid * 8 : (bid - NSEQ) * 32;
        for (int idx = tid; idx < 32 * 256; idx += THREADS) {
            int cl = idx >> 8, k0 = (idx & 255) * 2;
            float w0, w1;
            if (seq) {
                int grow = (cl >> 3) * NCH + nb32 + (cl & 7);
                w0 = W_hh[(size_t)grow * NCH + k0];
                w1 = W_hh[(size_t)grow * NCH + k0 + 1];
            } else {
                w0 = W_ih[(size_t)(nb32 + cl) * K_IH + 48 + k0];
                w1 = W_ih[(size_t)(nb32 + cl) * K_IH + 48 + k0 + 1];
            }
            uint32_t hi = pack2(w0, w1);
            int pos = wpos(cl, S_SEQ, k0);
            smw[pos] = hi; smw[pos + 2] = lo_res(hi, w0, w1);
        }
        __syncthreads();
    }

    if (seq) {
        // ================= SEQUENTIAL WORKER =================
        const int nb = bid * 8;
        const int n0 = nb + tig * 2;
        float cst[4] = {0.f, 0.f, 0.f, 0.f};
        const int gdep = (tid < 4) ? (tid * 16 + (bid >> 2)) : 0;

        for (int t = 0; t < TSTEPS; t++) {
            // parallel waits: g-flags (4 producers) + h-flags (64 producers)
            if (tid < 4) { while (ld_acq(&d_g_done[gdep]) < t) {} }
            else if (tid >= 64 && t > 0) { while (ld_acq(&d_h_done[tid - 64]) < t - 1) {} }
            __syncthreads();

            // accumulators = gate pre-activations G[t]
            const float* gp = d_G + (size_t)t * TB * G4;
            float acc[4][4];
#pragma unroll
            for (int gg = 0; gg < 4; gg++) {
                float2 v0 = __ldcg((const float2*)(gp + (size_t)row0 * G4 + gg * NCH + n0));
                float2 v1 = __ldcg((const float2*)(gp + (size_t)row1 * G4 + gg * NCH + n0));
                acc[gg][0] = v0.x; acc[gg][1] = v0.y;
                acc[gg][2] = v1.x; acc[gg][3] = v1.y;
            }

            if (t > 0) {
                const uint4* pq0 = d_Hq + ((size_t)(t - 1) * TB + row0) * 128 + tig;
                const uint4* pq1 = d_Hq + ((size_t)(t - 1) * TB + row1) * 128 + tig;
#pragma unroll 4
                for (int kt = 0; kt < 32; kt++) {
                    uint4 qa0 = pq0[kt * 4];
                    uint4 qa1 = pq1[kt * 4];
#pragma unroll
                    for (int gg = 0; gg < 4; gg++) {
                        const uint4 q = *(const uint4*)&smw[(gg * 8 + gid) * S_SEQ + kt * 16 + tig * 4];
                        mma16(acc[gg], qa0.x, qa1.x, qa0.y, qa1.y, q.x, q.y);   // hi*Whi
                        mma16(acc[gg], qa0.x, qa1.x, qa0.y, qa1.y, q.z, q.w);   // hi*Wlo
                        mma16(acc[gg], qa0.z, qa1.z, qa0.w, qa1.w, q.x, q.y);   // lo*Whi
                    }
                }
            }

            // activations (gate order i,f,g,o); publish h as interleaved uint4
            uint32_t hp[2], lp[2];
#pragma unroll
            for (int half = 0; half < 2; half++) {
                const int pA = half * 2, pB = half * 2 + 1;
                const int bb = row0 + half * 8;
                float c0 = sigm(acc[1][pA]) * cst[pA] + sigm(acc[0][pA]) * tanh_f(acc[2][pA]);
                float c1 = sigm(acc[1][pB]) * cst[pB] + sigm(acc[0][pB]) * tanh_f(acc[2][pB]);
                cst[pA] = c0; cst[pB] = c1;
                float h0 = sigm(acc[3][pA]) * tanh_f(c0);
                float h1 = sigm(acc[3][pB]) * tanh_f(c1);
                *(float2*)&out[(size_t)bb * HSTRIDE + (size_t)t * NCH + n0] = make_float2(h0, h1);
                hp[half] = pack2(h0, h1);
                lp[half] = lo_res(hp[half], h0, h1);
            }
            // pair (tig, tig^1) covers 4 consecutive n; even lane stores row0, odd row1
            uint32_t hp0p = __shfl_xor_sync(0xffffffffu, hp[0], 1);
            uint32_t lp0p = __shfl_xor_sync(0xffffffffu, lp[0], 1);
            uint32_t hp1p = __shfl_xor_sync(0xffffffffu, hp[1], 1);
            uint32_t lp1p = __shfl_xor_sync(0xffffffffu, lp[1], 1);
            {
                const int grp = (nb >> 2) + (tig >> 1);
                uint4 val;
                size_t rsel;
                if (tig & 1) { val = make_uint4(hp1p, hp[1], lp1p, lp[1]); rsel = row1; }
                else         { val = make_uint4(hp[0], hp0p, lp[0], lp0p); rsel = row0; }
                d_Hq[((size_t)t * TB + rsel) * 128 + grp] = val;
            }
            __syncthreads();
            if (tid == 0) st_rel(&d_h_done[bid], t);
        }
    } else {
        // ================= PRE-WORKER: G[u] += h_{u-32} @ W_ihh^T =================
        const int pid = bid - NSEQ;
        const int gb  = pid * 32;

        for (int u = 32; u < TSTEPS; u++) {
            // G0[u] (from xc_k) — independent of h, load before waiting
            const float* gp = d_G + (size_t)u * TB * G4;
            float acc[4][4];
#pragma unroll
            for (int nt = 0; nt < 4; nt++) {
                float2 v0 = __ldcg((const float2*)(gp + (size_t)row0 * G4 + gb + nt * 8 + tig * 2));
                float2 v1 = __ldcg((const float2*)(gp + (size_t)row1 * G4 + gb + nt * 8 + tig * 2));
                acc[nt][0] = v0.x; acc[nt][1] = v0.y;
                acc[nt][2] = v1.x; acc[nt][3] = v1.y;
            }

            if (tid < 64) { while (ld_acq(&d_h_done[tid]) < u - 32) {} }
            __syncthreads();

            const uint4* pq0 = d_Hq + ((size_t)(u - 32) * TB + row0) * 128 + tig;
            const uint4* pq1 = d_Hq + ((size_t)(u - 32) * TB + row1) * 128 + tig;
#pragma unroll 4
            for (int kt = 0; kt < 32; kt++) {
                uint4 qa0 = pq0[kt * 4];
                uint4 qa1 = pq1[kt * 4];
#pragma unroll
                for (int nt = 0; nt < 4; nt++) {
                    const uint4 q = *(const uint4*)&smw[(nt * 8 + gid) * S_SEQ + kt * 16 + tig * 4];
                    mma16(acc[nt], qa0.x, qa1.x, qa0.y, qa1.y, q.x, q.y);
                    mma16(acc[nt], qa0.x, qa1.x, qa0.y, qa1.y, q.z, q.w);
                    mma16(acc[nt], qa0.z, qa1.z, qa0.w, qa1.w, q.x, q.y);
                }
            }

            float* gw = d_G + (size_t)u * TB * G4;
#pragma unroll
            for (int nt = 0; nt < 4; nt++) {
                float* p0 = gw + (size_t)row0 * G4 + gb + nt * 8 + tig * 2;
                float* p1 = gw + (size_t)row1 * G4 + gb + nt * 8 + tig * 2;
                *(float2*)p0 = make_float2(acc[nt][0], acc[nt][1]);
                *(float2*)p1 = make_float2(acc[nt][2], acc[nt][3]);
            }
            __syncthreads();
            if (tid == 0) st_rel(&d_g_done[pid], u);
        }
    }
}

// ---------------- launch ----------------
extern "C" void kernel_launch(void* const* d_in, const int* in_sizes, int n_in,
                              void* d_out, int out_size) {
    const float* batch = (const float*)d_in[0];
    const float* W_ih  = (const float*)d_in[1];
    const float* W_hh  = (const float*)d_in[2];
    const float* b_ih  = (const float*)d_in[3];
    const float* b_hh  = (const float*)d_in[4];
    float* out = (float*)d_out;

    const int smem = 32 * S_SEQ * 4;   // 67584 B
    cudaFuncSetAttribute(lstm2d_k, cudaFuncAttributeMaxDynamicSharedMemorySize, smem);

    init_k<<<1, 64>>>();
    xc_k<<<dim3(64, 16), THREADS>>>(batch, W_ih, b_ih, b_hh);
    lstm2d_k<<<GRIDSZ, THREADS, smem>>>(W_ih, W_hh, out);
}